// round 9
// baseline (speedup 1.0000x reference)
#include <cuda_runtime.h>
#include <cuda_bf16.h>
#include <cstdint>

#define TT 16384
#define DD 2048
#define EE 64
#define KSEL 8
#define BR 128
#define KCH 32
#define NCH (DD / KCH)    // 64 chunks
#define TAU 5e-5f

#define ASTR 80           // A smem row stride (bytes), 16B-aligned, conflict-free
#define BSTR 80
#define ABUF (BR * ASTR)  // 10240 B per stage
#define BBUF (EE * BSTR)  // 5120 B per stage
#define OFF_AH 0
#define OFF_AM (2 * ABUF)             // 20480
#define OFF_BH (4 * ABUF)             // 40960
#define OFF_BM (4 * ABUF + 2 * BBUF)  // 51200
#define SMEM_TOTAL (4 * ABUF + 4 * BBUF)  // 61440

typedef unsigned long long ull;

// ---- device scratch ----
__device__ uint16_t g_wh[EE * DD];   // bf16 hi part of W, [e][d]
__device__ uint16_t g_wm[EE * DD];   // bf16 residual part
__device__ float g_cnt[EE];
__device__ float g_pn[EE];
__device__ int   g_nflag;
__device__ int   g_frows[TT];

static __device__ __forceinline__ uint32_t s2u(const void* p) {
    uint32_t a;
    asm("{ .reg .u64 t; cvta.to.shared.u64 t, %1; cvt.u32.u64 %0, t; }" : "=r"(a) : "l"(p));
    return a;
}

#define LDSM_X4(r0, r1, r2, r3, addr) \
    asm volatile("ldmatrix.sync.aligned.m8n8.x4.shared.b16 {%0,%1,%2,%3}, [%4];" \
                 : "=r"(r0), "=r"(r1), "=r"(r2), "=r"(r3) : "r"(addr))

#define MMA_BF16(c, a0, a1, a2, a3, b0, b1) \
    asm volatile("mma.sync.aligned.m16n8k16.row.col.f32.bf16.bf16.f32 " \
                 "{%0,%1,%2,%3},{%4,%5,%6,%7},{%8,%9},{%0,%1,%2,%3};" \
                 : "+f"((c)[0]), "+f"((c)[1]), "+f"((c)[2]), "+f"((c)[3]) \
                 : "r"(a0), "r"(a1), "r"(a2), "r"(a3), "r"(b0), "r"(b1))

static __device__ __forceinline__ uint32_t pack_bf16(float a, float b) {
    __nv_bfloat16 ha = __float2bfloat16(a), hb = __float2bfloat16(b);
    return (uint32_t)*(uint16_t*)&ha | ((uint32_t)*(uint16_t*)&hb << 16);
}

// ---------------------------------------------------------------------------
// prep: zero accumulators; split W into bf16 hi/residual, [e][d] row-major
// ---------------------------------------------------------------------------
__global__ void prep_kernel(const float* __restrict__ W) {
    int idx = blockIdx.x * blockDim.x + threadIdx.x;
    if (idx == 0) g_nflag = 0;
    if (idx < EE)          g_cnt[idx] = 0.f;
    else if (idx < 2 * EE) g_pn[idx - EE] = 0.f;
    if (idx < DD * EE) {
        float v = W[idx];
        __nv_bfloat16 h = __float2bfloat16(v);
        __nv_bfloat16 m = __float2bfloat16(v - __bfloat162float(h));
        g_wh[idx] = *(uint16_t*)&h;
        g_wm[idx] = *(uint16_t*)&m;
    }
}

extern __shared__ char dsm[];

// ---------------------------------------------------------------------------
// router: 128 blocks x 256 threads, 128 rows/block, HMMA bf16 3-pass split.
// ---------------------------------------------------------------------------
__global__ void __launch_bounds__(256, 1) router_kernel(
    const float* __restrict__ x,
    const float* __restrict__ bias,
    float* __restrict__ out)
{
    __shared__ float bias_s[EE];
    __shared__ float cnt_s[EE];

    const int t = threadIdx.x, wid = t >> 5, lane = t & 31;
    const int r0 = blockIdx.x * BR;
    const uint32_t sb = s2u(dsm);

    if (t < EE) { bias_s[t] = bias[t]; cnt_s[t] = 0.f; }

    // ---- staging maps
    const int ar = t >> 1, ah2 = t & 1;              // x: row, 16-float half
    const float4* xg = (const float4*)(x + (size_t)(r0 + ar) * DD + ah2 * 16);
    char* asth = dsm + OFF_AH + ar * ASTR + ah2 * 32;
    char* astm = dsm + OFF_AM + ar * ASTR + ah2 * 32;

    const int brr = t >> 2, bq = t & 3;              // W: row, 16B quarter
    const char* bsh = (const char*)g_wh + ((size_t)brr * DD) * 2 + bq * 16;
    const char* bsm = (const char*)g_wm + ((size_t)brr * DD) * 2 + bq * 16;
    const uint32_t bdh = sb + OFF_BH + brr * BSTR + bq * 16;
    const uint32_t bdm = sb + OFF_BM + brr * BSTR + bq * 16;

    // ---- ldmatrix lane addresses
    const int m0 = wid * 16;
    const uint32_t a_off = (uint32_t)((m0 + (lane & 15)) * ASTR + (lane >> 4) * 16);
    const uint32_t b_off = (uint32_t)(((lane & 7) + ((lane >> 4) << 3)) * BSTR
                                      + ((lane >> 3) & 1) * 16);

    float acc[8][4];
    #pragma unroll
    for (int i = 0; i < 8; i++)
        #pragma unroll
        for (int g = 0; g < 4; g++) acc[i][g] = 0.f;

    float4 rx[4];
    #pragma unroll
    for (int j = 0; j < 4; j++) rx[j] = xg[j];

    for (int c = 0; c < NCH; c++) {
        const int b = c & 1;

        // stage A: split x -> bf16 h/m, STS.64 per float4
        #pragma unroll
        for (int j = 0; j < 4; j++) {
            float4 v = rx[j];
            float fh0 = __bfloat162float(__float2bfloat16(v.x));
            float fh1 = __bfloat162float(__float2bfloat16(v.y));
            float fh2 = __bfloat162float(__float2bfloat16(v.z));
            float fh3 = __bfloat162float(__float2bfloat16(v.w));
            uint32_t hlo = pack_bf16(v.x, v.y), hhi = pack_bf16(v.z, v.w);
            uint32_t mlo = pack_bf16(v.x - fh0, v.y - fh1);
            uint32_t mhi = pack_bf16(v.z - fh2, v.w - fh3);
            *(ull*)(asth + b * ABUF + j * 8) = (ull)hlo | ((ull)hhi << 32);
            *(ull*)(astm + b * ABUF + j * 8) = (ull)mlo | ((ull)mhi << 32);
        }
        // stage B: cp.async W chunk (64B per expert-row per array)
        {
            const char* s0 = bsh + (size_t)c * KCH * 2;
            const char* s1 = bsm + (size_t)c * KCH * 2;
            asm volatile("cp.async.cg.shared.global [%0], [%1], 16;"
                         :: "r"(bdh + b * BBUF), "l"(s0));
            asm volatile("cp.async.cg.shared.global [%0], [%1], 16;"
                         :: "r"(bdm + b * BBUF), "l"(s1));
            asm volatile("cp.async.commit_group;");
        }
        // prefetch next x chunk
        if (c + 1 < NCH) {
            #pragma unroll
            for (int j = 0; j < 4; j++) rx[j] = xg[(size_t)(c + 1) * (KCH / 4) + j];
        }
        asm volatile("cp.async.wait_group 0;" ::: "memory");
        __syncthreads();

        // ---- compute chunk c (2 k16 steps)
        #pragma unroll
        for (int ks = 0; ks < 2; ks++) {
            const uint32_t ao = sb + b * ABUF + a_off + ks * 32;
            uint32_t ah0, ah1, ah2r, ah3, am0, am1, am2, am3;
            LDSM_X4(ah0, ah1, ah2r, ah3, ao + OFF_AH);
            LDSM_X4(am0, am1, am2, am3, ao + OFF_AM);
            #pragma unroll
            for (int nt = 0; nt < 4; nt++) {
                const uint32_t bo = sb + b * BBUF + b_off + nt * (16 * BSTR) + ks * 32;
                uint32_t bh0, bh1, bh2, bh3, bm0, bm1, bm2, bm3;
                LDSM_X4(bh0, bh1, bh2, bh3, bo + OFF_BH);
                LDSM_X4(bm0, bm1, bm2, bm3, bo + OFF_BM);
                MMA_BF16(acc[nt * 2],     ah0, ah1, ah2r, ah3, bh0, bh1);
                MMA_BF16(acc[nt * 2],     ah0, ah1, ah2r, ah3, bm0, bm1);
                MMA_BF16(acc[nt * 2],     am0, am1, am2,  am3, bh0, bh1);
                MMA_BF16(acc[nt * 2 + 1], ah0, ah1, ah2r, ah3, bh2, bh3);
                MMA_BF16(acc[nt * 2 + 1], ah0, ah1, ah2r, ah3, bm2, bm3);
                MMA_BF16(acc[nt * 2 + 1], am0, am1, am2,  am3, bh2, bh3);
            }
        }
    }
    __syncthreads();   // all compute done before L overlay

    // ---- logits -> L[128][68] overlay
    float* Lf = (float*)dsm;
    {
        const int rr = m0 + (lane >> 2);
        const int cc = (lane & 3) * 2;
        #pragma unroll
        for (int ti = 0; ti < 8; ti++) {
            const int n0 = ti * 8 + cc;
            Lf[rr * 68 + n0]           = acc[ti][0];
            Lf[rr * 68 + n0 + 1]       = acc[ti][1];
            Lf[(rr + 8) * 68 + n0]     = acc[ti][2];
            Lf[(rr + 8) * 68 + n0 + 1] = acc[ti][3];
        }
    }
    __syncthreads();

    // ---- per-row: sigmoid, top-9 margin test, finalize or flag
    if (t < BR) {
        float* Lr = Lf + t * 68;
        float ssum = 0.f;
        #pragma unroll
        for (int e = 0; e < EE; e++) {
            float a = 1.f / (1.f + expf(-Lr[e]));
            Lr[e] = a; ssum += a;
        }
        ull mask = 0ULL;
        float v9[9]; int i9[9];
        #pragma unroll
        for (int k = 0; k < 9; k++) {
            float best = -3.4e38f; int bi = 0;
            for (int e = 0; e < EE; e++) {
                if ((mask >> e) & 1ULL) continue;
                float v = Lr[e] + bias_s[e];
                if (v > best) { best = v; bi = e; }
            }
            mask |= 1ULL << bi; v9[k] = best; i9[k] = bi;
        }
        float ming = 3.4e38f;
        #pragma unroll
        for (int k = 0; k < 8; k++) ming = fminf(ming, v9[k] - v9[k + 1]);
        if (ming < TAU) {
            int s = atomicAdd(&g_nflag, 1);
            g_frows[s] = r0 + t;
            #pragma unroll
            for (int e = 0; e < EE; e++) Lr[e] = 0.f;   // exclude from P partials
        } else {
            float gsum = 0.f; float gv[KSEL];
            #pragma unroll
            for (int k = 0; k < KSEL; k++) {
                gv[k] = Lr[i9[k]]; gsum += gv[k];
                atomicAdd(&cnt_s[i9[k]], 1.f);
            }
            float inv = 1.f / (gsum + 1e-9f);
            size_t rg = (size_t)(r0 + t);
            #pragma unroll
            for (int k = 0; k < KSEL; k++) {
                out[rg * KSEL + k]                     = gv[k] * inv;
                out[(size_t)TT * KSEL + rg * KSEL + k] = (float)i9[k];
            }
            float pinv = 1.f / (ssum + 1e-9f);
            #pragma unroll
            for (int e = 0; e < EE; e++) Lr[e] *= pinv;
        }
    }
    __syncthreads();

    // ---- per-expert partial sums of affinity_norm
    {
        const int e = t & 63, seg = t >> 6;
        float s = 0.f;
        #pragma unroll
        for (int r = seg * 32; r < seg * 32 + 32; r++) s += Lf[r * 68 + e];
        atomicAdd(&g_pn[e], s);
    }
    if (t < EE) atomicAdd(&g_cnt[t], cnt_s[t]);
}

// ---------------------------------------------------------------------------
// patch: exact sequential-d fp32 recompute (R5/R7 numerics) for flagged rows
// ---------------------------------------------------------------------------
__global__ void __launch_bounds__(64) patch_kernel(
    const float* __restrict__ x, const float* __restrict__ W,
    const float* __restrict__ bias, float* __restrict__ out)
{
    __shared__ float xs[DD];
    __shared__ float aff[EE];
    __shared__ float pinv_s;
    const int e = threadIdx.x;
    const int nf = g_nflag;
    for (int i = blockIdx.x; i < nf; i += gridDim.x) {
        const int r = g_frows[i];
        for (int q = e; q < DD / 4; q += 64)
            ((float4*)xs)[q] = ((const float4*)(x + (size_t)r * DD))[q];
        __syncthreads();
        const float4* wr = (const float4*)(W + (size_t)e * DD);
        float acc = 0.f;
        #pragma unroll 4
        for (int q = 0; q < DD / 4; q++) {
            float4 w = wr[q];
            acc = fmaf(xs[4 * q + 0], w.x, acc);
            acc = fmaf(xs[4 * q + 1], w.y, acc);
            acc = fmaf(xs[4 * q + 2], w.z, acc);
            acc = fmaf(xs[4 * q + 3], w.w, acc);
        }
        aff[e] = 1.f / (1.f + expf(-acc));
        __syncthreads();
        if (e == 0) {
            float ssum = 0.f;
            for (int k = 0; k < EE; k++) ssum += aff[k];
            ull mask = 0ULL; float gsum = 0.f;
            float gv[KSEL]; int gi[KSEL];
            for (int k = 0; k < KSEL; k++) {
                float best = -3.4e38f; int bi = 0;
                for (int j = 0; j < EE; j++) {
                    if ((mask >> j) & 1ULL) continue;
                    float v = aff[j] + bias[j];
                    if (v > best) { best = v; bi = j; }
                }
                mask |= 1ULL << bi; gi[k] = bi;
                float a = aff[bi]; gv[k] = a; gsum += a;
                atomicAdd(&g_cnt[bi], 1.f);
            }
            float inv = 1.f / (gsum + 1e-9f);
            for (int k = 0; k < KSEL; k++) {
                out[(size_t)r * KSEL + k]                     = gv[k] * inv;
                out[(size_t)TT * KSEL + (size_t)r * KSEL + k] = (float)gi[k];
            }
            pinv_s = 1.f / (ssum + 1e-9f);
        }
        __syncthreads();
        atomicAdd(&g_pn[e], aff[e] * pinv_s);
        __syncthreads();
    }
}

// ---------------------------------------------------------------------------
__global__ void finalize_kernel(float* __restrict__ out) {
    __shared__ float red[EE];
    const int e = threadIdx.x;
    red[e] = g_cnt[e] * g_pn[e];
    __syncthreads();
    if (e == 0) {
        float s = 0.f;
        for (int i = 0; i < EE; i++) s += red[i];
        double loss = (double)s * 1e-4 * 64.0 / (8.0 * 16384.0) / 16384.0;
        out[(size_t)2 * TT * KSEL] = (float)loss;
    }
}

// ---------------------------------------------------------------------------
extern "C" void kernel_launch(void* const* d_in, const int* in_sizes, int n_in,
                              void* d_out, int out_size) {
    const float* x    = (const float*)d_in[0];
    const float* W    = (const float*)d_in[1];
    const float* bias = (const float*)d_in[2];
    float* out = (float*)d_out;

    static bool attr_done = false;
    if (!attr_done) {
        cudaFuncSetAttribute(router_kernel,
                             cudaFuncAttributeMaxDynamicSharedMemorySize, SMEM_TOTAL);
        attr_done = true;
    }

    prep_kernel<<<512, 256>>>(W);
    router_kernel<<<TT / BR, 256, SMEM_TOTAL>>>(x, bias, out);
    patch_kernel<<<2048, 64>>>(x, W, bias, out);
    finalize_kernel<<<1, 64>>>(out);
}